// round 4
// baseline (speedup 1.0000x reference)
#include <cuda_runtime.h>
#include <cuda_fp16.h>
#include <cstdint>

// ======================= problem constants =======================
static constexpr int MDIM = 16384;   // 8*2048
static constexpr int NDIM = 4096;
static constexpr int KDIM = 4096;

static constexpr int BM = 128;
static constexpr int BN = 256;
static constexpr int BK = 64;            // 64 fp16 = 128B per row
static constexpr int NSTAGE = 3;
static constexpr int NIT = KDIM / BK;    // 64

static constexpr int A_BYTES = BM * BK * 2;            // 16384
static constexpr int B_BYTES = BN * BK * 2;            // 32768
static constexpr int STAGE_BYTES = A_BYTES + B_BYTES;  // 49152

static constexpr uint32_t SM_BIAS   = 0;     // 256 floats = 1024B
static constexpr uint32_t SM_STAGE0 = 1024;
static constexpr uint32_t SMEM_TOTAL = SM_STAGE0 + NSTAGE * STAGE_BYTES; // 148480

// ======================= scratch (static device globals) =========
__device__ __align__(256) __half g_xh[(size_t)MDIM * KDIM];  // 128 MB
__device__ __align__(256) __half g_wb[(size_t)NDIM * KDIM];  //  32 MB

// ======================= helpers =================================
__device__ __forceinline__ uint32_t smem_u32(const void* p) {
    uint32_t a;
    asm("{ .reg .u64 t; cvta.to.shared.u64 t, %1; cvt.u32.u64 %0, t; }"
        : "=r"(a) : "l"(p));
    return a;
}

__device__ __forceinline__ void cpasync16(uint32_t saddr, const void* g) {
    asm volatile("cp.async.cg.shared.global [%0], [%1], 16;" :: "r"(saddr), "l"(g));
}

__device__ __forceinline__ void ldsm_x4(uint32_t& r0, uint32_t& r1,
                                        uint32_t& r2, uint32_t& r3, uint32_t addr) {
    asm volatile("ldmatrix.sync.aligned.m8n8.x4.shared.b16 {%0,%1,%2,%3}, [%4];"
                 : "=r"(r0), "=r"(r1), "=r"(r2), "=r"(r3) : "r"(addr));
}

__device__ __forceinline__ void mma16816(float* c, const uint32_t* a,
                                         const uint32_t* b) {
    asm volatile(
        "mma.sync.aligned.m16n8k16.row.col.f32.f16.f16.f32 "
        "{%0,%1,%2,%3}, {%4,%5,%6,%7}, {%8,%9}, {%0,%1,%2,%3};"
        : "+f"(c[0]), "+f"(c[1]), "+f"(c[2]), "+f"(c[3])
        : "r"(a[0]), "r"(a[1]), "r"(a[2]), "r"(a[3]), "r"(b[0]), "r"(b[1]));
}

// ======================= prep kernels ============================
__global__ void __launch_bounds__(256) binarize_w_kernel(const float4* __restrict__ w, int n4) {
    uint2* o = reinterpret_cast<uint2*>(g_wb);
    int i = blockIdx.x * blockDim.x + threadIdx.x;
    int st = gridDim.x * blockDim.x;
    for (; i < n4; i += st) {
        float4 v = w[i];
        __half2 a = __floats2half2_rn(v.x >= 0.f ? 1.f : -1.f, v.y >= 0.f ? 1.f : -1.f);
        __half2 b = __floats2half2_rn(v.z >= 0.f ? 1.f : -1.f, v.w >= 0.f ? 1.f : -1.f);
        union { __half2 h; uint32_t u; } pa, pb;
        pa.h = a; pb.h = b;
        o[i] = make_uint2(pa.u, pb.u);
    }
}

__global__ void __launch_bounds__(256) convert_x_kernel(const float4* __restrict__ x, int n4) {
    uint2* o = reinterpret_cast<uint2*>(g_xh);
    int i = blockIdx.x * blockDim.x + threadIdx.x;
    int st = gridDim.x * blockDim.x;
    for (; i < n4; i += st) {
        float4 v = x[i];
        __half2 a = __floats2half2_rn(v.x, v.y);
        __half2 b = __floats2half2_rn(v.z, v.w);
        union { __half2 h; uint32_t u; } pa, pb;
        pa.h = a; pb.h = b;
        o[i] = make_uint2(pa.u, pb.u);
    }
}

// ======================= GEMM kernel =============================
// 256 threads = 8 warps, warp layout 2 (M) x 4 (N), warp tile 64x64.
__global__ void __launch_bounds__(256, 1) gemm_kernel(const float* __restrict__ bias,
                                                      float* __restrict__ out) {
    extern __shared__ char smem[];
    const uint32_t smem_base = smem_u32(smem);
    const int tid = threadIdx.x;
    const int wid = tid >> 5;
    const int lane = tid & 31;

    // grouped rasterization for L2 locality: groups of 8 pm rows x all 16 pn
    constexpr int NTN = NDIM / BN;  // 16
    constexpr int GM = 8;
    int pid = blockIdx.x;
    int group = pid / (GM * NTN);
    int rem = pid % (GM * NTN);
    int pm = group * GM + (rem % GM);
    int pn = rem / GM;
    const int m0 = pm * BM;
    const int n0 = pn * BN;

    // bias -> smem
    reinterpret_cast<float*>(smem + SM_BIAS)[tid] = bias[n0 + tid];

    // ---- async stage loader ----
    auto load_stage = [&](int s, int j) {
        uint32_t sA = smem_base + SM_STAGE0 + (uint32_t)s * STAGE_BYTES;
        uint32_t sB = sA + A_BYTES;
        const __half* gA = &g_xh[(size_t)m0 * KDIM + (size_t)j * BK];
        const __half* gB = &g_wb[(size_t)n0 * KDIM + (size_t)j * BK];
        // A: 128 rows x 8 chunks of 16B = 1024, 4 per thread
        #pragma unroll
        for (int i = 0; i < 4; i++) {
            int q = tid + i * 256;
            int r = q >> 3, c = q & 7;
            uint32_t so = (uint32_t)(r * 128 + ((c * 16) ^ ((r & 7) * 16)));
            cpasync16(sA + so, gA + (size_t)r * KDIM + c * 8);
        }
        // B: 256 rows x 8 chunks = 2048, 8 per thread
        #pragma unroll
        for (int i = 0; i < 8; i++) {
            int q = tid + i * 256;
            int r = q >> 3, c = q & 7;
            uint32_t so = (uint32_t)(r * 128 + ((c * 16) ^ ((r & 7) * 16)));
            cpasync16(sB + so, gB + (size_t)r * KDIM + c * 8);
        }
    };

    // prologue: stages 0..NSTAGE-2
    #pragma unroll
    for (int j = 0; j < NSTAGE - 1; j++) {
        load_stage(j, j);
        asm volatile("cp.async.commit_group;");
    }

    // ---- per-warp fragment addressing ----
    const int warpM = wid & 1;          // 0..1
    const int warpN = wid >> 1;         // 0..3
    const int l16 = lane & 15;
    const uint32_t colb = (uint32_t)((lane >> 4) * 16);

    uint32_t rowOffA[4], xorA[4];       // 4 m-frags (m16)
    #pragma unroll
    for (int mf = 0; mf < 4; mf++) {
        int row = warpM * 64 + mf * 16 + l16;
        rowOffA[mf] = (uint32_t)(row * 128);
        xorA[mf] = (uint32_t)((row & 7) * 16);
    }
    uint32_t rowOffB[4], xorB[4];       // 4 n16 groups covering 64 N
    #pragma unroll
    for (int nh = 0; nh < 4; nh++) {
        int row = warpN * 64 + nh * 16 + l16;
        rowOffB[nh] = (uint32_t)(row * 128);
        xorB[nh] = (uint32_t)((row & 7) * 16);
    }

    float acc[4][8][4];                 // [m-frag][n-frag][4]
    #pragma unroll
    for (int mf = 0; mf < 4; mf++)
        #pragma unroll
        for (int nf = 0; nf < 8; nf++)
            #pragma unroll
            for (int k = 0; k < 4; k++) acc[mf][nf][k] = 0.f;

    // ---- main loop (single sync per iter) ----
    for (int it = 0; it < NIT; ++it) {
        asm volatile("cp.async.wait_group %0;" :: "n"(NSTAGE - 2));
        __syncthreads();   // stage it%3 ready AND all warps done reading it-1's buf

        int j = it + NSTAGE - 1;
        if (j < NIT) load_stage(j % NSTAGE, j);
        asm volatile("cp.async.commit_group;");

        int cur = it % NSTAGE;
        uint32_t sA = smem_base + SM_STAGE0 + (uint32_t)cur * STAGE_BYTES;
        uint32_t sB = sA + A_BYTES;

        #pragma unroll
        for (int ks = 0; ks < BK / 16; ks++) {
            const uint32_t kcol = (uint32_t)(ks * 32) + colb;
            uint32_t a[4][4];
            #pragma unroll
            for (int mf = 0; mf < 4; mf++)
                ldsm_x4(a[mf][0], a[mf][1], a[mf][2], a[mf][3],
                        sA + rowOffA[mf] + (kcol ^ xorA[mf]));
            uint32_t br[4][4];
            #pragma unroll
            for (int nh = 0; nh < 4; nh++)
                ldsm_x4(br[nh][0], br[nh][1], br[nh][2], br[nh][3],
                        sB + rowOffB[nh] + (kcol ^ xorB[nh]));
            #pragma unroll
            for (int mf = 0; mf < 4; mf++) {
                #pragma unroll
                for (int nf = 0; nf < 8; nf++) {
                    uint32_t b2[2];
                    b2[0] = br[nf >> 1][nf & 1];
                    b2[1] = br[nf >> 1][(nf & 1) + 2];
                    mma16816(acc[mf][nf], a[mf], b2);
                }
            }
        }
    }

    // ---- epilogue ----
    const float* sb = reinterpret_cast<const float*>(smem + SM_BIAS);
    const int groupid = lane >> 2;
    const int tid4 = lane & 3;
    #pragma unroll
    for (int mf = 0; mf < 4; mf++) {
        int m = m0 + warpM * 64 + mf * 16 + groupid;
        #pragma unroll
        for (int nf = 0; nf < 8; nf++) {
            int nl = warpN * 64 + nf * 8 + tid4 * 2;   // local col in tile
            int n = n0 + nl;
            float2 v0;
            v0.x = acc[mf][nf][0] + sb[nl];
            v0.y = acc[mf][nf][1] + sb[nl + 1];
            *reinterpret_cast<float2*>(out + (size_t)m * NDIM + n) = v0;
            float2 v1;
            v1.x = acc[mf][nf][2] + sb[nl];
            v1.y = acc[mf][nf][3] + sb[nl + 1];
            *reinterpret_cast<float2*>(out + (size_t)(m + 8) * NDIM + n) = v1;
        }
    }
}

// ======================= launch ==================================
extern "C" void kernel_launch(void* const* d_in, const int* in_sizes, int n_in,
                              void* d_out, int out_size) {
    (void)in_sizes; (void)n_in; (void)out_size;
    const float* x    = (const float*)d_in[0];
    const float* w    = (const float*)d_in[1];
    const float* bias = (const float*)d_in[2];
    float* out = (float*)d_out;

    convert_x_kernel<<<8192, 256>>>((const float4*)x, (int)((size_t)MDIM * KDIM / 4));
    binarize_w_kernel<<<4096, 256>>>((const float4*)w, (int)((size_t)NDIM * KDIM / 4));

    cudaFuncSetAttribute(gemm_kernel, cudaFuncAttributeMaxDynamicSharedMemorySize,
                         (int)SMEM_TOTAL);
    int grid = (MDIM / BM) * (NDIM / BN);  // 2048
    gemm_kernel<<<grid, 256, SMEM_TOTAL>>>(bias, out);
}

// round 5
// speedup vs baseline: 1.0441x; 1.0441x over previous
#include <cuda_runtime.h>
#include <cuda_fp16.h>
#include <cstdint>

// ======================= problem constants =======================
static constexpr int MDIM = 16384;   // 8*2048
static constexpr int NDIM = 4096;
static constexpr int KDIM = 4096;

static constexpr int BM = 128;
static constexpr int BN = 256;
static constexpr int BK = 64;            // 64 fp16 = 128B per row
static constexpr int NSTAGE = 3;
static constexpr int NIT = KDIM / BK;    // 64

static constexpr int A_BYTES = BM * BK * 2;            // 16384
static constexpr int B_BYTES = BN * BK * 2;            // 32768
static constexpr int STAGE_BYTES = A_BYTES + B_BYTES;  // 49152

static constexpr uint32_t SM_BIAS   = 0;     // 256 floats = 1024B
static constexpr uint32_t SM_STAGE0 = 1024;
static constexpr uint32_t SMEM_TOTAL = SM_STAGE0 + NSTAGE * STAGE_BYTES; // 148480

static constexpr int NTHREADS = 512;     // 16 warps, 4(M) x 4(N)

// ======================= scratch (static device globals) =========
__device__ __align__(256) __half g_xh[(size_t)MDIM * KDIM];  // 128 MB
__device__ __align__(256) __half g_wb[(size_t)NDIM * KDIM];  //  32 MB

// ======================= helpers =================================
__device__ __forceinline__ uint32_t smem_u32(const void* p) {
    uint32_t a;
    asm("{ .reg .u64 t; cvta.to.shared.u64 t, %1; cvt.u32.u64 %0, t; }"
        : "=r"(a) : "l"(p));
    return a;
}

__device__ __forceinline__ void cpasync16(uint32_t saddr, const void* g) {
    asm volatile("cp.async.cg.shared.global [%0], [%1], 16;" :: "r"(saddr), "l"(g));
}

__device__ __forceinline__ void ldsm_x4(uint32_t& r0, uint32_t& r1,
                                        uint32_t& r2, uint32_t& r3, uint32_t addr) {
    asm volatile("ldmatrix.sync.aligned.m8n8.x4.shared.b16 {%0,%1,%2,%3}, [%4];"
                 : "=r"(r0), "=r"(r1), "=r"(r2), "=r"(r3) : "r"(addr));
}

__device__ __forceinline__ void mma16816(float* c, const uint32_t* a,
                                         const uint32_t* b) {
    asm volatile(
        "mma.sync.aligned.m16n8k16.row.col.f32.f16.f16.f32 "
        "{%0,%1,%2,%3}, {%4,%5,%6,%7}, {%8,%9}, {%0,%1,%2,%3};"
        : "+f"(c[0]), "+f"(c[1]), "+f"(c[2]), "+f"(c[3])
        : "r"(a[0]), "r"(a[1]), "r"(a[2]), "r"(a[3]), "r"(b[0]), "r"(b[1]));
}

// ======================= fused prep kernel =======================
// blocks [0, XB): convert x -> fp16; blocks [XB, XB+WB): binarize w -> +-1 fp16
static constexpr int XB = 8192;
static constexpr int WB = 4096;

__global__ void __launch_bounds__(256) prep_kernel(const float4* __restrict__ x,
                                                   const float4* __restrict__ w) {
    if (blockIdx.x < XB) {
        const int n4 = (int)((size_t)MDIM * KDIM / 4);
        uint2* o = reinterpret_cast<uint2*>(g_xh);
        int i = blockIdx.x * 256 + threadIdx.x;
        int st = XB * 256;
        for (; i < n4; i += st) {
            float4 v = x[i];
            __half2 a = __floats2half2_rn(v.x, v.y);
            __half2 b = __floats2half2_rn(v.z, v.w);
            union { __half2 h; uint32_t u; } pa, pb;
            pa.h = a; pb.h = b;
            o[i] = make_uint2(pa.u, pb.u);
        }
    } else {
        const int n4 = (int)((size_t)NDIM * KDIM / 4);
        uint2* o = reinterpret_cast<uint2*>(g_wb);
        int i = (blockIdx.x - XB) * 256 + threadIdx.x;
        int st = WB * 256;
        for (; i < n4; i += st) {
            float4 v = w[i];
            __half2 a = __floats2half2_rn(v.x >= 0.f ? 1.f : -1.f, v.y >= 0.f ? 1.f : -1.f);
            __half2 b = __floats2half2_rn(v.z >= 0.f ? 1.f : -1.f, v.w >= 0.f ? 1.f : -1.f);
            union { __half2 h; uint32_t u; } pa, pb;
            pa.h = a; pb.h = b;
            o[i] = make_uint2(pa.u, pb.u);
        }
    }
}

// ======================= GEMM kernel =============================
// 512 threads = 16 warps, warp layout 4 (M) x 4 (N), warp tile 32x64.
__global__ void __launch_bounds__(NTHREADS, 1) gemm_kernel(const float* __restrict__ bias,
                                                           float* __restrict__ out) {
    extern __shared__ char smem[];
    const uint32_t smem_base = smem_u32(smem);
    const int tid = threadIdx.x;
    const int wid = tid >> 5;
    const int lane = tid & 31;

    // grouped rasterization for L2 locality: groups of 8 pm rows x all 16 pn
    constexpr int NTN = NDIM / BN;  // 16
    constexpr int GM = 8;
    int pid = blockIdx.x;
    int group = pid / (GM * NTN);
    int rem = pid % (GM * NTN);
    int pm = group * GM + (rem % GM);
    int pn = rem / GM;
    const int m0 = pm * BM;
    const int n0 = pn * BN;

    // bias -> smem
    if (tid < BN) reinterpret_cast<float*>(smem + SM_BIAS)[tid] = bias[n0 + tid];

    // ---- async stage loader (512 threads) ----
    auto load_stage = [&](int s, int j) {
        uint32_t sA = smem_base + SM_STAGE0 + (uint32_t)s * STAGE_BYTES;
        uint32_t sB = sA + A_BYTES;
        const __half* gA = &g_xh[(size_t)m0 * KDIM + (size_t)j * BK];
        const __half* gB = &g_wb[(size_t)n0 * KDIM + (size_t)j * BK];
        // A: 128 rows x 8 chunks of 16B = 1024, 2 per thread
        #pragma unroll
        for (int i = 0; i < 2; i++) {
            int q = tid + i * NTHREADS;
            int r = q >> 3, c = q & 7;
            uint32_t so = (uint32_t)(r * 128 + ((c * 16) ^ ((r & 7) * 16)));
            cpasync16(sA + so, gA + (size_t)r * KDIM + c * 8);
        }
        // B: 256 rows x 8 chunks = 2048, 4 per thread
        #pragma unroll
        for (int i = 0; i < 4; i++) {
            int q = tid + i * NTHREADS;
            int r = q >> 3, c = q & 7;
            uint32_t so = (uint32_t)(r * 128 + ((c * 16) ^ ((r & 7) * 16)));
            cpasync16(sB + so, gB + (size_t)r * KDIM + c * 8);
        }
    };

    // prologue: stages 0..NSTAGE-2
    #pragma unroll
    for (int j = 0; j < NSTAGE - 1; j++) {
        load_stage(j, j);
        asm volatile("cp.async.commit_group;");
    }

    // ---- per-warp fragment addressing ----
    const int warpM = wid & 3;          // 0..3 (M)
    const int warpN = wid >> 2;         // 0..3 (N)
    const int l16 = lane & 15;
    const uint32_t colb = (uint32_t)((lane >> 4) * 16);

    uint32_t rowOffA[2], xorA[2];       // 2 m-frags (m16) -> 32 rows
    #pragma unroll
    for (int mf = 0; mf < 2; mf++) {
        int row = warpM * 32 + mf * 16 + l16;
        rowOffA[mf] = (uint32_t)(row * 128);
        xorA[mf] = (uint32_t)((row & 7) * 16);
    }
    uint32_t rowOffB[4], xorB[4];       // 4 n16 groups -> 64 cols
    #pragma unroll
    for (int nh = 0; nh < 4; nh++) {
        int row = warpN * 64 + nh * 16 + l16;
        rowOffB[nh] = (uint32_t)(row * 128);
        xorB[nh] = (uint32_t)((row & 7) * 16);
    }

    float acc[2][8][4];                 // [m-frag][n-frag][4]
    #pragma unroll
    for (int mf = 0; mf < 2; mf++)
        #pragma unroll
        for (int nf = 0; nf < 8; nf++)
            #pragma unroll
            for (int k = 0; k < 4; k++) acc[mf][nf][k] = 0.f;

    // ---- main loop (single sync per iter) ----
    for (int it = 0; it < NIT; ++it) {
        asm volatile("cp.async.wait_group %0;" :: "n"(NSTAGE - 2));
        __syncthreads();   // stage ready AND prior-iter reads of the overwrite target done

        int j = it + NSTAGE - 1;
        if (j < NIT) load_stage(j % NSTAGE, j);
        asm volatile("cp.async.commit_group;");

        int cur = it % NSTAGE;
        uint32_t sA = smem_base + SM_STAGE0 + (uint32_t)cur * STAGE_BYTES;
        uint32_t sB = sA + A_BYTES;

        #pragma unroll
        for (int ks = 0; ks < BK / 16; ks++) {
            const uint32_t kcol = (uint32_t)(ks * 32) + colb;
            uint32_t a[2][4];
            #pragma unroll
            for (int mf = 0; mf < 2; mf++)
                ldsm_x4(a[mf][0], a[mf][1], a[mf][2], a[mf][3],
                        sA + rowOffA[mf] + (kcol ^ xorA[mf]));
            uint32_t br[4][4];
            #pragma unroll
            for (int nh = 0; nh < 4; nh++)
                ldsm_x4(br[nh][0], br[nh][1], br[nh][2], br[nh][3],
                        sB + rowOffB[nh] + (kcol ^ xorB[nh]));
            #pragma unroll
            for (int mf = 0; mf < 2; mf++) {
                #pragma unroll
                for (int nf = 0; nf < 8; nf++) {
                    uint32_t b2[2];
                    b2[0] = br[nf >> 1][nf & 1];
                    b2[1] = br[nf >> 1][(nf & 1) + 2];
                    mma16816(acc[mf][nf], a[mf], b2);
                }
            }
        }
    }

    // ---- epilogue ----
    const float* sb = reinterpret_cast<const float*>(smem + SM_BIAS);
    const int groupid = lane >> 2;
    const int tid4 = lane & 3;
    #pragma unroll
    for (int mf = 0; mf < 2; mf++) {
        int m = m0 + warpM * 32 + mf * 16 + groupid;
        #pragma unroll
        for (int nf = 0; nf < 8; nf++) {
            int nl = warpN * 64 + nf * 8 + tid4 * 2;   // local col in tile
            int n = n0 + nl;
            float2 v0;
            v0.x = acc[mf][nf][0] + sb[nl];
            v0.y = acc[mf][nf][1] + sb[nl + 1];
            *reinterpret_cast<float2*>(out + (size_t)m * NDIM + n) = v0;
            float2 v1;
            v1.x = acc[mf][nf][2] + sb[nl];
            v1.y = acc[mf][nf][3] + sb[nl + 1];
            *reinterpret_cast<float2*>(out + (size_t)(m + 8) * NDIM + n) = v1;
        }
    }
}

// ======================= launch ==================================
extern "C" void kernel_launch(void* const* d_in, const int* in_sizes, int n_in,
                              void* d_out, int out_size) {
    (void)in_sizes; (void)n_in; (void)out_size;
    const float* x    = (const float*)d_in[0];
    const float* w    = (const float*)d_in[1];
    const float* bias = (const float*)d_in[2];
    float* out = (float*)d_out;

    prep_kernel<<<XB + WB, 256>>>((const float4*)x, (const float4*)w);

    cudaFuncSetAttribute(gemm_kernel, cudaFuncAttributeMaxDynamicSharedMemorySize,
                         (int)SMEM_TOTAL);
    int grid = (MDIM / BM) * (NDIM / BN);  // 2048
    gemm_kernel<<<grid, NTHREADS, SMEM_TOTAL>>>(bias, out);
}

// round 9
// speedup vs baseline: 1.1161x; 1.0689x over previous
#include <cuda_runtime.h>
#include <cuda_fp16.h>
#include <cstdint>

// ======================= problem constants =======================
static constexpr int MDIM = 16384;   // 8*2048
static constexpr int NDIM = 4096;
static constexpr int KDIM = 4096;

static constexpr int BM = 128;
static constexpr int BN = 128;
static constexpr int BK = 64;            // 64 fp16 = 128B per row
static constexpr int NSTAGE = 3;
static constexpr int NIT = KDIM / BK;    // 64

static constexpr int A_BYTES = BM * BK * 2;            // 16384
static constexpr int B_BYTES = BN * BK * 2;            // 16384
static constexpr int STAGE_BYTES = A_BYTES + B_BYTES;  // 32768

static constexpr uint32_t SM_BIAS   = 0;     // 128 floats
static constexpr uint32_t SM_STAGE0 = 1024;
static constexpr uint32_t SMEM_TOTAL = SM_STAGE0 + NSTAGE * STAGE_BYTES; // 99328

// ======================= scratch (static device globals) =========
__device__ __align__(256) __half g_xh[(size_t)MDIM * KDIM];  // 128 MB
__device__ __align__(256) __half g_wb[(size_t)NDIM * KDIM];  //  32 MB

// ======================= helpers =================================
__device__ __forceinline__ uint32_t smem_u32(const void* p) {
    uint32_t a;
    asm("{ .reg .u64 t; cvta.to.shared.u64 t, %1; cvt.u32.u64 %0, t; }"
        : "=r"(a) : "l"(p));
    return a;
}

__device__ __forceinline__ void cpasync16(uint32_t saddr, const void* g) {
    asm volatile("cp.async.cg.shared.global [%0], [%1], 16;" :: "r"(saddr), "l"(g));
}

__device__ __forceinline__ void ldsm_x4(uint32_t& r0, uint32_t& r1,
                                        uint32_t& r2, uint32_t& r3, uint32_t addr) {
    asm volatile("ldmatrix.sync.aligned.m8n8.x4.shared.b16 {%0,%1,%2,%3}, [%4];"
                 : "=r"(r0), "=r"(r1), "=r"(r2), "=r"(r3) : "r"(addr));
}

__device__ __forceinline__ void mma16816(float* c, const uint32_t* a,
                                         const uint32_t* b) {
    asm volatile(
        "mma.sync.aligned.m16n8k16.row.col.f32.f16.f16.f32 "
        "{%0,%1,%2,%3}, {%4,%5,%6,%7}, {%8,%9}, {%0,%1,%2,%3};"
        : "+f"(c[0]), "+f"(c[1]), "+f"(c[2]), "+f"(c[3])
        : "r"(a[0]), "r"(a[1]), "r"(a[2]), "r"(a[3]), "r"(b[0]), "r"(b[1]));
}

// ======================= fused prep kernel =======================
static constexpr int XB = 8192;
static constexpr int WB = 4096;

__global__ void __launch_bounds__(256) prep_kernel(const float4* __restrict__ x,
                                                   const float4* __restrict__ w) {
    if (blockIdx.x < XB) {
        const int n4 = (int)((size_t)MDIM * KDIM / 4);
        uint2* o = reinterpret_cast<uint2*>(g_xh);
        int i = blockIdx.x * 256 + threadIdx.x;
        int st = XB * 256;
        for (; i < n4; i += st) {
            float4 v = x[i];
            __half2 a = __floats2half2_rn(v.x, v.y);
            __half2 b = __floats2half2_rn(v.z, v.w);
            union { __half2 h; uint32_t u; } pa, pb;
            pa.h = a; pb.h = b;
            o[i] = make_uint2(pa.u, pb.u);
        }
    } else {
        const int n4 = (int)((size_t)NDIM * KDIM / 4);
        uint2* o = reinterpret_cast<uint2*>(g_wb);
        int i = (blockIdx.x - XB) * 256 + threadIdx.x;
        int st = WB * 256;
        for (; i < n4; i += st) {
            float4 v = w[i];
            __half2 a = __floats2half2_rn(v.x >= 0.f ? 1.f : -1.f, v.y >= 0.f ? 1.f : -1.f);
            __half2 b = __floats2half2_rn(v.z >= 0.f ? 1.f : -1.f, v.w >= 0.f ? 1.f : -1.f);
            union { __half2 h; uint32_t u; } pa, pb;
            pa.h = a; pb.h = b;
            o[i] = make_uint2(pa.u, pb.u);
        }
    }
}

// ======================= GEMM kernel =============================
// 256 threads = 8 warps, warp layout 2 (M) x 4 (N), warp tile 64x32.
// 2 CTAs/SM. Warp-staggered ks order to de-phase LDSM bursts.
__global__ void __launch_bounds__(256, 2) gemm_kernel(const float* __restrict__ bias,
                                                      float* __restrict__ out) {
    extern __shared__ char smem[];
    const uint32_t smem_base = smem_u32(smem);
    const int tid = threadIdx.x;
    const int wid = tid >> 5;
    const int lane = tid & 31;

    // grouped rasterization for L2 locality
    constexpr int NTN = NDIM / BN;  // 32
    constexpr int GM = 8;
    int pid = blockIdx.x;
    int group = pid / (GM * NTN);
    int rem = pid % (GM * NTN);
    int pm = group * GM + (rem % GM);
    int pn = rem / GM;
    const int m0 = pm * BM;
    const int n0 = pn * BN;

    if (tid < BN) reinterpret_cast<float*>(smem + SM_BIAS)[tid] = bias[n0 + tid];

    // ---- async stage loader ----
    auto load_stage = [&](int s, int j) {
        uint32_t sA = smem_base + SM_STAGE0 + (uint32_t)s * STAGE_BYTES;
        uint32_t sB = sA + A_BYTES;
        const __half* gA = &g_xh[(size_t)m0 * KDIM + (size_t)j * BK];
        const __half* gB = &g_wb[(size_t)n0 * KDIM + (size_t)j * BK];
        #pragma unroll
        for (int i = 0; i < 4; i++) {
            int q = tid + i * 256;
            int r = q >> 3, c = q & 7;
            uint32_t so = (uint32_t)(r * 128 + ((c * 16) ^ ((r & 7) * 16)));
            cpasync16(sA + so, gA + (size_t)r * KDIM + c * 8);
        }
        #pragma unroll
        for (int i = 0; i < 4; i++) {
            int q = tid + i * 256;
            int r = q >> 3, c = q & 7;
            uint32_t so = (uint32_t)(r * 128 + ((c * 16) ^ ((r & 7) * 16)));
            cpasync16(sB + so, gB + (size_t)r * KDIM + c * 8);
        }
    };

    #pragma unroll
    for (int j = 0; j < NSTAGE - 1; j++) {
        load_stage(j, j);
        asm volatile("cp.async.commit_group;");
    }

    // ---- per-warp fragment addressing ----
    const int warpM = wid & 1;          // 0..1
    const int warpN = wid >> 1;         // 0..3
    const int l16 = lane & 15;
    const uint32_t colb = (uint32_t)((lane >> 4) * 16);

    uint32_t rowOffA[4], xorA[4];       // 4 m16 frags -> 64 rows
    #pragma unroll
    for (int mf = 0; mf < 4; mf++) {
        int row = warpM * 64 + mf * 16 + l16;
        rowOffA[mf] = (uint32_t)(row * 128);
        xorA[mf] = (uint32_t)((row & 7) * 16);
    }
    uint32_t rowOffB[2], xorB[2];       // 2 n16 groups -> 32 cols
    #pragma unroll
    for (int nh = 0; nh < 2; nh++) {
        int row = warpN * 32 + nh * 16 + l16;
        rowOffB[nh] = (uint32_t)(row * 128);
        xorB[nh] = (uint32_t)((row & 7) * 16);
    }

    float acc[4][4][4];
    #pragma unroll
    for (int mf = 0; mf < 4; mf++)
        #pragma unroll
        for (int nf = 0; nf < 4; nf++)
            #pragma unroll
            for (int k = 0; k < 4; k++) acc[mf][nf][k] = 0.f;

    // one ks block: 6 LDSM.x4 + 16 HMMA
    auto compute_ks = [&](uint32_t sA, uint32_t sB, int ks) {
        const uint32_t kcol = (uint32_t)(ks * 32) + colb;
        uint32_t a[4][4];
        #pragma unroll
        for (int mf = 0; mf < 4; mf++)
            ldsm_x4(a[mf][0], a[mf][1], a[mf][2], a[mf][3],
                    sA + rowOffA[mf] + (kcol ^ xorA[mf]));
        uint32_t br[2][4];
        #pragma unroll
        for (int nh = 0; nh < 2; nh++)
            ldsm_x4(br[nh][0], br[nh][1], br[nh][2], br[nh][3],
                    sB + rowOffB[nh] + (kcol ^ xorB[nh]));
        #pragma unroll
        for (int mf = 0; mf < 4; mf++) {
            #pragma unroll
            for (int nf = 0; nf < 4; nf++) {
                uint32_t b2[2];
                b2[0] = br[nf >> 1][nf & 1];
                b2[1] = br[nf >> 1][(nf & 1) + 2];
                mma16816(acc[mf][nf], a[mf], b2);
            }
        }
    };

    // ---- main loop ----
    const int ks0 = wid & 3;    // warp-dependent phase
    for (int it = 0; it < NIT; ++it) {
        asm volatile("cp.async.wait_group %0;" :: "n"(NSTAGE - 2));
        __syncthreads();

        int cur = it % NSTAGE;
        uint32_t sA = smem_base + SM_STAGE0 + (uint32_t)cur * STAGE_BYTES;
        uint32_t sB = sA + A_BYTES;

        // first ks block (staggered per warp) before issuing prefetch
        compute_ks(sA, sB, ks0);

        int j = it + NSTAGE - 1;
        if (j < NIT) load_stage(j % NSTAGE, j);
        asm volatile("cp.async.commit_group;");

        #pragma unroll
        for (int kk = 1; kk < 4; kk++)
            compute_ks(sA, sB, (ks0 + kk) & 3);
    }

    // ---- epilogue ----
    const float* sb = reinterpret_cast<const float*>(smem + SM_BIAS);
    const int groupid = lane >> 2;
    const int tid4 = lane & 3;
    #pragma unroll
    for (int mf = 0; mf < 4; mf++) {
        int m = m0 + warpM * 64 + mf * 16 + groupid;
        #pragma unroll
        for (int nf = 0; nf < 4; nf++) {
            int nl = warpN * 32 + nf * 8 + tid4 * 2;
            int n = n0 + nl;
            float2 v0;
            v0.x = acc[mf][nf][0] + sb[nl];
            v0.y = acc[mf][nf][1] + sb[nl + 1];
            *reinterpret_cast<float2*>(out + (size_t)m * NDIM + n) = v0;
            float2 v1;
            v1.x = acc[mf][nf][2] + sb[nl];
            v1.y = acc[mf][nf][3] + sb[nl + 1];
            *reinterpret_cast<float2*>(out + (size_t)(m + 8) * NDIM + n) = v1;
        }
    }
}

// ======================= launch ==================================
extern "C" void kernel_launch(void* const* d_in, const int* in_sizes, int n_in,
                              void* d_out, int out_size) {
    (void)in_sizes; (void)n_in; (void)out_size;
    const float* x    = (const float*)d_in[0];
    const float* w    = (const float*)d_in[1];
    const float* bias = (const float*)d_in[2];
    float* out = (float*)d_out;

    prep_kernel<<<XB + WB, 256>>>((const float4*)x, (const float4*)w);

    cudaFuncSetAttribute(gemm_kernel, cudaFuncAttributeMaxDynamicSharedMemorySize,
                         (int)SMEM_TOTAL);
    int grid = (MDIM / BM) * (NDIM / BN);  // 4096
    gemm_kernel<<<grid, 256, SMEM_TOTAL>>>(bias, out);
}